// round 1
// baseline (speedup 1.0000x reference)
#include <cuda_runtime.h>
#include <math.h>

#define BATCH 64
#define CH    512
#define NPIX  256
#define HEADS 8
#define HD    64

// Scratch (no cudaMalloc allowed) -----------------------------------------
__device__ float g_qkv[(size_t)BATCH * 3 * CH * NPIX];  // [b][o][p], o in [0,1536)
__device__ float g_att[(size_t)BATCH * CH * NPIX];      // [b][c][p]

// ---------------------------------------------------------------------------
// GEMM: Y[b][o][p] = sum_c W[o][c] * X[b][c][p] + bias[o]
// Tile: 64(M) x 64(N) x 16(K), 256 threads, 4x4 register tile per thread.
// Grid: (NPIX/64, M/64, BATCH)
// ---------------------------------------------------------------------------
template <int M, int K>
__global__ __launch_bounds__(256, 1) void gemm_bias(
    const float* __restrict__ W, const float* __restrict__ X,
    const float* __restrict__ bias, float* __restrict__ Y)
{
    __shared__ float Ws[16][64];   // [k][m]
    __shared__ float Xs[16][68];   // [k][n] padded

    const int tid = threadIdx.x;
    const int tx = tid & 15;       // n-group
    const int ty = tid >> 4;       // m-group
    const int p0 = blockIdx.x * 64;
    const int m0 = blockIdx.y * 64;
    const int b  = blockIdx.z;

    const int wr = tid >> 2;            // 0..63 : W row within tile
    const int wc = (tid & 3) * 4;       // 0..12 : W col quad within k-tile
    const float* Wp = W + (size_t)(m0 + wr) * K + wc;
    const int xr = tid >> 4;            // 0..15 : X row within k-tile
    const int xc = (tid & 15) * 4;      // 0..60
    const float* Xp = X + ((size_t)b * K + xr) * NPIX + p0 + xc;

    float acc[4][4];
    #pragma unroll
    for (int i = 0; i < 4; i++)
        #pragma unroll
        for (int j = 0; j < 4; j++) acc[i][j] = 0.f;

    for (int k0 = 0; k0 < K; k0 += 16) {
        float4 w4 = *(const float4*)(Wp + k0);
        float4 x4 = *(const float4*)(Xp + (size_t)k0 * NPIX);
        __syncthreads();
        Ws[wc + 0][wr] = w4.x;
        Ws[wc + 1][wr] = w4.y;
        Ws[wc + 2][wr] = w4.z;
        Ws[wc + 3][wr] = w4.w;
        *(float4*)&Xs[xr][xc] = x4;
        __syncthreads();

        #pragma unroll
        for (int kk = 0; kk < 16; kk++) {
            float4 a4 = *(const float4*)&Ws[kk][ty * 4];
            float4 b4 = *(const float4*)&Xs[kk][tx * 4];
            float a[4] = {a4.x, a4.y, a4.z, a4.w};
            float bb[4] = {b4.x, b4.y, b4.z, b4.w};
            #pragma unroll
            for (int i = 0; i < 4; i++)
                #pragma unroll
                for (int j = 0; j < 4; j++)
                    acc[i][j] += a[i] * bb[j];
        }
    }

    #pragma unroll
    for (int i = 0; i < 4; i++) {
        const int o = m0 + ty * 4 + i;
        const float bv = bias[o];
        float4 r;
        r.x = acc[i][0] + bv;
        r.y = acc[i][1] + bv;
        r.z = acc[i][2] + bv;
        r.w = acc[i][3] + bv;
        *(float4*)(Y + ((size_t)b * M + o) * NPIX + p0 + tx * 4) = r;
    }
}

// ---------------------------------------------------------------------------
// Attention: per CTA = (batch b, head h, 64-query tile).
//   S[n][m] = (sum_d Q[d][n] K[d][m]) * hd^-0.5 + rel[h][nh-mh+15][nw-mw+15]
//   P = softmax_m(S);  O[d][n] = sum_m P[n][m] V[d][m]
// Grid: (4, HEADS, BATCH), 256 threads, ~217 KB dynamic smem.
// ---------------------------------------------------------------------------
#define QS_OFF   0
#define KS_OFF   (QS_OFF + 64 * 64)          // 4096
#define VS_OFF   (KS_OFF + 64 * 256)         // 20480
#define SS_OFF   (VS_OFF + 256 * 68)         // 37888
#define RS_OFF   (SS_OFF + 64 * 257)         // 54336
#define PR_OFF   (RS_OFF + 961)              // 55297
#define RV_OFF   (PR_OFF + 256)              // 55553
#define ATTN_SMEM_FLOATS (RV_OFF + 64)       // 55617
#define ATTN_SMEM_BYTES  (ATTN_SMEM_FLOATS * 4)

__global__ __launch_bounds__(256, 1) void attn_kernel(const float* __restrict__ rel)
{
    extern __shared__ float sm[];
    float* Qs = sm + QS_OFF;   // [d][n]  stride 64
    float* Ks = sm + KS_OFF;   // [d][m]  stride 256
    float* Vs = sm + VS_OFF;   // [m][d]  stride 68 (transposed, padded)
    float* Ss = sm + SS_OFF;   // [n][m]  stride 257
    float* Rs = sm + RS_OFF;   // rel_pos_enc[h] : 31x31
    float* pr = sm + PR_OFF;   // [n][4] partial reduce
    float* rv = sm + RV_OFF;   // [n] row value

    const int tid = threadIdx.x;
    const int n0 = blockIdx.x * 64;
    const int h  = blockIdx.y;
    const int b  = blockIdx.z;

    const float* qkv = g_qkv + (size_t)b * (3 * CH * NPIX);
    const float* qg = qkv + (h * HD) * NPIX;
    const float* kg = qkv + (CH + h * HD) * NPIX;
    const float* vg = qkv + (2 * CH + h * HD) * NPIX;

    // ---- Load tiles ----
    #pragma unroll
    for (int it = 0; it < 4; it++) {                 // Q : 64x64
        int i = tid + it * 256;
        int d = i >> 4, nq = (i & 15) * 4;
        *(float4*)&Qs[d * 64 + nq] = *(const float4*)&qg[d * NPIX + n0 + nq];
    }
    #pragma unroll
    for (int it = 0; it < 16; it++) {                // K : 64x256
        int i = tid + it * 256;
        int d = i >> 6, mq = (i & 63) * 4;
        *(float4*)&Ks[d * 256 + mq] = *(const float4*)&kg[d * NPIX + mq];
    }
    #pragma unroll
    for (int it = 0; it < 16; it++) {                // V : transpose to [m][d]
        int i = tid + it * 256;
        int d = i >> 6, mq = (i & 63) * 4;
        float4 v4 = *(const float4*)&vg[d * NPIX + mq];
        Vs[(mq + 0) * 68 + d] = v4.x;
        Vs[(mq + 1) * 68 + d] = v4.y;
        Vs[(mq + 2) * 68 + d] = v4.z;
        Vs[(mq + 3) * 68 + d] = v4.w;
    }
    for (int i = tid; i < 961; i += 256) Rs[i] = rel[h * 961 + i];
    __syncthreads();

    // ---- Phase 2: S = Q^T K (each thread: 1 query row n, 64 m-values) ----
    const int n  = tid & 63;
    const int mb = tid >> 6;       // 0..3
    const int m0 = mb * 64;

    float acc[64];
    #pragma unroll
    for (int i = 0; i < 64; i++) acc[i] = 0.f;

    #pragma unroll 2
    for (int d = 0; d < 64; d++) {
        float qv = Qs[d * 64 + n];
        const float4* kr = (const float4*)&Ks[d * 256 + m0];
        #pragma unroll
        for (int q = 0; q < 16; q++) {
            float4 k4 = kr[q];
            acc[q * 4 + 0] += qv * k4.x;
            acc[q * 4 + 1] += qv * k4.y;
            acc[q * 4 + 2] += qv * k4.z;
            acc[q * 4 + 3] += qv * k4.w;
        }
    }

    // ---- bias + scale, then softmax over m ----
    const int ng = n0 + n, nh = ng >> 4, nw = ng & 15;
    float lmax = -1e30f;
    #pragma unroll
    for (int i = 0; i < 64; i++) {
        int m = m0 + i, mh = m >> 4, mw = m & 15;
        float bv = Rs[(nh - mh + 15) * 31 + (nw - mw + 15)];
        float s = acc[i] * 0.125f + bv;      // hd^-0.5 = 1/8
        acc[i] = s;
        lmax = fmaxf(lmax, s);
    }
    pr[n * 4 + mb] = lmax;
    __syncthreads();
    if (tid < 64)
        rv[tid] = fmaxf(fmaxf(pr[tid * 4 + 0], pr[tid * 4 + 1]),
                        fmaxf(pr[tid * 4 + 2], pr[tid * 4 + 3]));
    __syncthreads();
    const float rm = rv[n];
    float lsum = 0.f;
    #pragma unroll
    for (int i = 0; i < 64; i++) {
        float e = __expf(acc[i] - rm);
        acc[i] = e;
        lsum += e;
    }
    pr[n * 4 + mb] = lsum;
    __syncthreads();
    if (tid < 64)
        rv[tid] = 1.f / (pr[tid * 4 + 0] + pr[tid * 4 + 1] +
                         pr[tid * 4 + 2] + pr[tid * 4 + 3]);
    __syncthreads();
    const float inv = rv[n];
    #pragma unroll
    for (int i = 0; i < 64; i++) Ss[n * 257 + m0 + i] = acc[i] * inv;
    __syncthreads();

    // ---- Phase 4: O[d][n] = sum_m P[n][m] V[d][m] ----
    const int dg = (tid & 15) * 4;        // 4 d's
    const int nb = (tid >> 4) * 4;        // 4 n's
    float o2[4][4];
    #pragma unroll
    for (int j = 0; j < 4; j++)
        #pragma unroll
        for (int i = 0; i < 4; i++) o2[j][i] = 0.f;

    #pragma unroll 4
    for (int m = 0; m < 256; m++) {
        float4 v4 = *(const float4*)&Vs[m * 68 + dg];
        #pragma unroll
        for (int j = 0; j < 4; j++) {
            float s = Ss[(nb + j) * 257 + m];
            o2[j][0] += s * v4.x;
            o2[j][1] += s * v4.y;
            o2[j][2] += s * v4.z;
            o2[j][3] += s * v4.w;
        }
    }

    float* og = g_att + ((size_t)b * CH + h * HD) * NPIX + n0;
    #pragma unroll
    for (int j = 0; j < 4; j++)
        #pragma unroll
        for (int i = 0; i < 4; i++)
            og[(size_t)(dg + i) * NPIX + nb + j] = o2[j][i];
}

// ---------------------------------------------------------------------------
extern "C" void kernel_launch(void* const* d_in, const int* in_sizes, int n_in,
                              void* d_out, int out_size)
{
    const float* x      = (const float*)d_in[0];
    const float* qkv_w  = (const float*)d_in[1];
    const float* qkv_b  = (const float*)d_in[2];
    const float* out_w  = (const float*)d_in[3];
    const float* out_b  = (const float*)d_in[4];
    const float* rel    = (const float*)d_in[5];
    float* out = (float*)d_out;

    void* p_qkv = nullptr;
    void* p_att = nullptr;
    cudaGetSymbolAddress(&p_qkv, g_qkv);
    cudaGetSymbolAddress(&p_att, g_att);

    cudaFuncSetAttribute(attn_kernel,
                         cudaFuncAttributeMaxDynamicSharedMemorySize,
                         ATTN_SMEM_BYTES);

    // 1) QKV projection: [1536,512] @ [512,256] per batch (+bias)
    gemm_bias<3 * CH, CH><<<dim3(NPIX / 64, (3 * CH) / 64, BATCH), 256>>>(
        qkv_w, x, qkv_b, (float*)p_qkv);

    // 2) Attention with relative-position bias
    attn_kernel<<<dim3(NPIX / 64, HEADS, BATCH), 256, ATTN_SMEM_BYTES>>>(rel);

    // 3) Output projection: [512,512] @ [512,256] per batch (+bias)
    gemm_bias<CH, CH><<<dim3(NPIX / 64, CH / 64, BATCH), 256>>>(
        out_w, (const float*)p_att, out_b, out);
}

// round 3
// speedup vs baseline: 1.7462x; 1.7462x over previous
#include <cuda_runtime.h>
#include <cstdint>
#include <math.h>

#define BATCH 64
#define CH    512
#define NPIX  256
#define HEADS 8
#define HD    64

// Scratch (no cudaMalloc allowed) -----------------------------------------
__device__ float g_qkv[(size_t)BATCH * 3 * CH * NPIX];  // [b][o][p]
__device__ float g_att[(size_t)BATCH * CH * NPIX];      // [b][c][p]

// ======================= helpers ==========================================
__device__ __forceinline__ uint32_t smem_to_u32(const void* p) {
    uint32_t a;
    asm("{ .reg .u64 t; cvta.to.shared.u64 t, %1; cvt.u32.u64 %0, t; }"
        : "=r"(a) : "l"(p));
    return a;
}

// pack two floats -> bf16x2 (hi half = f_hi, lo half = f_lo)
__device__ __forceinline__ uint32_t pack_bf16x2(float f_hi, float f_lo) {
    uint32_t r;
    asm("cvt.rn.bf16x2.f32 %0, %1, %2;" : "=r"(r) : "f"(f_hi), "f"(f_lo));
    return r;
}

__device__ __forceinline__ void ldm_x4(uint32_t* r, uint32_t addr) {
    asm volatile("ldmatrix.sync.aligned.m8n8.x4.shared.b16 {%0,%1,%2,%3}, [%4];"
        : "=r"(r[0]), "=r"(r[1]), "=r"(r[2]), "=r"(r[3]) : "r"(addr));
}

__device__ __forceinline__ void mma_bf16(float* c, const uint32_t* a,
                                         const uint32_t* b) {
    asm volatile(
        "mma.sync.aligned.m16n8k16.row.col.f32.bf16.bf16.f32 "
        "{%0,%1,%2,%3}, {%4,%5,%6,%7}, {%8,%9}, {%0,%1,%2,%3};"
        : "+f"(c[0]), "+f"(c[1]), "+f"(c[2]), "+f"(c[3])
        : "r"(a[0]), "r"(a[1]), "r"(a[2]), "r"(a[3]), "r"(b[0]), "r"(b[1]));
}

// exp via FMA pipe (degree-5 2^f poly + exponent bit insert), |relerr|<3e-6
__device__ __forceinline__ float fast_exp(float t) {
    float y = t * 1.4426950408889634f;
    y = fmaxf(y, -126.0f);
    int ni = __float2int_rn(y);
    float f = y - (float)ni;
    float p = 1.3333558146428443e-3f;
    p = fmaf(p, f, 9.618129842071803e-3f);
    p = fmaf(p, f, 5.550410866482158e-2f);
    p = fmaf(p, f, 2.402265069591007e-1f);
    p = fmaf(p, f, 6.931471805599453e-1f);
    p = fmaf(p, f, 1.0f);
    return __uint_as_float(__float_as_uint(p) + ((uint32_t)ni << 23));
}

// ---------------------------------------------------------------------------
// GEMM via mma.sync bf16 (2-way split, 3 terms):
//   Y[b][o][p] = sum_c W[o][c] * X[b][c][p] + bias[o]
// CTA tile 64(M=o) x 64(N=p), K chunks of 32. 128 threads = 4 warps (2x2),
// warp tile 32x32. A = W[m][k] row-major; B stored transposed Bt[n][k].
// SMEM rows: 32 k-halfs (64B) + 16B pad = 80B stride (16B-aligned rows).
// ---------------------------------------------------------------------------
#define A_HI 0
#define A_LO 5120
#define B_HI 10240
#define B_LO 15360
#define GEMM_SMEM_BYTES 20480

template <int M>
__global__ __launch_bounds__(128, 1) void gemm_mma(
    const float* __restrict__ W, const float* __restrict__ X,
    const float* __restrict__ bias, float* __restrict__ Y)
{
    __shared__ __align__(128) char smem[GEMM_SMEM_BYTES];
    const uint32_t sb = smem_to_u32(smem);

    const int tid = threadIdx.x;
    const int wid = tid >> 5;
    const int lid = tid & 31;
    const int wm = wid >> 1;          // 0..1
    const int wn = wid & 1;           // 0..1
    const int p0 = blockIdx.x * 64;
    const int m0 = blockIdx.y * 64;
    const int b  = blockIdx.z;

    // ---- global load pointers ----
    // A: thread -> (m = tid/8 (+16i), kq = tid%8), float4 per row-chunk
    const int am  = tid >> 3;
    const int akq = tid & 7;
    const float* wp = W + (size_t)(m0 + am) * CH + akq * 4;
    // B: thread -> (n = tid%64, g = tid/64), 16 scalar k-loads
    const int bn = tid & 63;
    const int bg = tid >> 6;
    const float* xp = X + (size_t)b * CH * NPIX + p0 + bn;

    // ---- ldmatrix per-thread addresses ----
    const uint32_t aoff = (uint32_t)(wm * 32 + (lid & 15)) * 80 + (lid >> 4) * 16;
    const uint32_t aAH0 = sb + A_HI + aoff;
    const uint32_t aAL0 = sb + A_LO + aoff;
    const int q = lid >> 3;
    const uint32_t boff =
        (uint32_t)(wn * 32 + ((q >> 1) & 1) * 8 + (lid & 7)) * 80 + (q & 1) * 16;
    const uint32_t aBH0 = sb + B_HI + boff;
    const uint32_t aBL0 = sb + B_LO + boff;

    float acc[2][4][4];
    #pragma unroll
    for (int mi = 0; mi < 2; mi++)
        #pragma unroll
        for (int nj = 0; nj < 4; nj++)
            #pragma unroll
            for (int e = 0; e < 4; e++) acc[mi][nj][e] = 0.f;

    // ---- prologue prefetch chunk 0 ----
    float4 ra[4];
    float  rb[16];
    #pragma unroll
    for (int i = 0; i < 4; i++)
        ra[i] = *(const float4*)(wp + (size_t)(16 * i) * CH);
    #pragma unroll
    for (int j = 0; j < 16; j++)
        rb[j] = xp[(size_t)(bg * 16 + j) * NPIX];

    #pragma unroll 1
    for (int c = 0; c < 16; c++) {
        // ---- STS current chunk (hi/lo split) ----
        #pragma unroll
        for (int i = 0; i < 4; i++) {
            uint32_t h0 = pack_bf16x2(ra[i].y, ra[i].x);
            uint32_t h1 = pack_bf16x2(ra[i].w, ra[i].z);
            float hx = __uint_as_float(h0 << 16);
            float hy = __uint_as_float(h0 & 0xFFFF0000u);
            float hz = __uint_as_float(h1 << 16);
            float hw = __uint_as_float(h1 & 0xFFFF0000u);
            uint32_t l0 = pack_bf16x2(ra[i].y - hy, ra[i].x - hx);
            uint32_t l1 = pack_bf16x2(ra[i].w - hw, ra[i].z - hz);
            uint32_t off = (uint32_t)(am + 16 * i) * 80 + akq * 8;
            *(uint2*)(smem + A_HI + off) = make_uint2(h0, h1);
            *(uint2*)(smem + A_LO + off) = make_uint2(l0, l1);
        }
        {
            uint32_t base = (uint32_t)bn * 80 + bg * 32;
            #pragma unroll
            for (int qq = 0; qq < 4; qq++) {
                float f0 = rb[qq * 4 + 0], f1 = rb[qq * 4 + 1];
                float f2 = rb[qq * 4 + 2], f3 = rb[qq * 4 + 3];
                uint32_t h0 = pack_bf16x2(f1, f0);
                uint32_t h1 = pack_bf16x2(f3, f2);
                float g0 = __uint_as_float(h0 << 16);
                float g1 = __uint_as_float(h0 & 0xFFFF0000u);
                float g2 = __uint_as_float(h1 << 16);
                float g3 = __uint_as_float(h1 & 0xFFFF0000u);
                uint32_t l0 = pack_bf16x2(f1 - g1, f0 - g0);
                uint32_t l1 = pack_bf16x2(f3 - g3, f2 - g2);
                *(uint2*)(smem + B_HI + base + qq * 8) = make_uint2(h0, h1);
                *(uint2*)(smem + B_LO + base + qq * 8) = make_uint2(l0, l1);
            }
        }
        __syncthreads();

        // ---- prefetch next chunk (overlaps mma) ----
        if (c < 15) {
            const int k0 = (c + 1) * 32;
            #pragma unroll
            for (int i = 0; i < 4; i++)
                ra[i] = *(const float4*)(wp + (size_t)(16 * i) * CH + k0);
            #pragma unroll
            for (int j = 0; j < 16; j++)
                rb[j] = xp[(size_t)(k0 + bg * 16 + j) * NPIX];
        }

        // ---- compute: 2 k-steps of 16 ----
        #pragma unroll
        for (int ks = 0; ks < 2; ks++) {
            const uint32_t kb = ks * 32;
            uint32_t ah[2][4], al[2][4], bh[2][4], bl[2][4];
            ldm_x4(ah[0], aAH0 + kb);
            ldm_x4(ah[1], aAH0 + 16 * 80 + kb);
            ldm_x4(al[0], aAL0 + kb);
            ldm_x4(al[1], aAL0 + 16 * 80 + kb);
            ldm_x4(bh[0], aBH0 + kb);
            ldm_x4(bh[1], aBH0 + 16 * 80 + kb);
            ldm_x4(bl[0], aBL0 + kb);
            ldm_x4(bl[1], aBL0 + 16 * 80 + kb);

            #pragma unroll
            for (int mi = 0; mi < 2; mi++)
                #pragma unroll
                for (int nj = 0; nj < 4; nj++) {
                    const uint32_t* bhp = &bh[nj >> 1][(nj & 1) * 2];
                    const uint32_t* blp = &bl[nj >> 1][(nj & 1) * 2];
                    mma_bf16(acc[mi][nj], ah[mi], bhp);
                    mma_bf16(acc[mi][nj], ah[mi], blp);
                    mma_bf16(acc[mi][nj], al[mi], bhp);
                }
        }
        __syncthreads();
    }

    // ---- epilogue ----
    #pragma unroll
    for (int mi = 0; mi < 2; mi++) {
        const int rr = wm * 32 + mi * 16 + (lid >> 2);
        const float bv0 = __ldg(&bias[m0 + rr]);
        const float bv1 = __ldg(&bias[m0 + rr + 8]);
        float* y0 = Y + ((size_t)b * M + m0 + rr) * NPIX + p0 + wn * 32 + (lid & 3) * 2;
        float* y1 = y0 + 8 * NPIX;
        #pragma unroll
        for (int nj = 0; nj < 4; nj++) {
            float2 v0 = make_float2(acc[mi][nj][0] + bv0, acc[mi][nj][1] + bv0);
            float2 v1 = make_float2(acc[mi][nj][2] + bv1, acc[mi][nj][3] + bv1);
            *(float2*)(y0 + nj * 8) = v0;
            *(float2*)(y1 + nj * 8) = v1;
        }
    }
}

// ---------------------------------------------------------------------------
// Attention: per CTA = (batch b, head h, 64-query tile).
// ---------------------------------------------------------------------------
#define QS_OFF   0
#define KS_OFF   (QS_OFF + 64 * 64)
#define VS_OFF   (KS_OFF + 64 * 256)
#define SS_OFF   (VS_OFF + 256 * 68)
#define RS_OFF   (SS_OFF + 64 * 257)
#define PR_OFF   (RS_OFF + 961)
#define RV_OFF   (PR_OFF + 256)
#define ATTN_SMEM_FLOATS (RV_OFF + 64)
#define ATTN_SMEM_BYTES  (ATTN_SMEM_FLOATS * 4)

__global__ __launch_bounds__(256, 1) void attn_kernel(const float* __restrict__ rel)
{
    extern __shared__ float sm[];
    float* Qs = sm + QS_OFF;
    float* Ks = sm + KS_OFF;
    float* Vs = sm + VS_OFF;
    float* Ss = sm + SS_OFF;
    float* Rs = sm + RS_OFF;
    float* pr = sm + PR_OFF;
    float* rv = sm + RV_OFF;

    const int tid = threadIdx.x;
    const int n0 = blockIdx.x * 64;
    const int h  = blockIdx.y;
    const int b  = blockIdx.z;

    const float* qkv = g_qkv + (size_t)b * (3 * CH * NPIX);
    const float* qg = qkv + (h * HD) * NPIX;
    const float* kg = qkv + (CH + h * HD) * NPIX;
    const float* vg = qkv + (2 * CH + h * HD) * NPIX;

    #pragma unroll
    for (int it = 0; it < 4; it++) {
        int i = tid + it * 256;
        int d = i >> 4, nq = (i & 15) * 4;
        *(float4*)&Qs[d * 64 + nq] = *(const float4*)&qg[d * NPIX + n0 + nq];
    }
    #pragma unroll
    for (int it = 0; it < 16; it++) {
        int i = tid + it * 256;
        int d = i >> 6, mq = (i & 63) * 4;
        *(float4*)&Ks[d * 256 + mq] = *(const float4*)&kg[d * NPIX + mq];
    }
    #pragma unroll
    for (int it = 0; it < 16; it++) {
        int i = tid + it * 256;
        int d = i >> 6, mq = (i & 63) * 4;
        float4 v4 = *(const float4*)&vg[d * NPIX + mq];
        Vs[(mq + 0) * 68 + d] = v4.x;
        Vs[(mq + 1) * 68 + d] = v4.y;
        Vs[(mq + 2) * 68 + d] = v4.z;
        Vs[(mq + 3) * 68 + d] = v4.w;
    }
    for (int i = tid; i < 961; i += 256) Rs[i] = rel[h * 961 + i];
    __syncthreads();

    const int n  = tid & 63;
    const int mb = tid >> 6;
    const int m0 = mb * 64;

    float acc[64];
    #pragma unroll
    for (int i = 0; i < 64; i++) acc[i] = 0.f;

    #pragma unroll 2
    for (int d = 0; d < 64; d++) {
        float qv = Qs[d * 64 + n];
        const float4* kr = (const float4*)&Ks[d * 256 + m0];
        #pragma unroll
        for (int qq = 0; qq < 16; qq++) {
            float4 k4 = kr[qq];
            acc[qq * 4 + 0] += qv * k4.x;
            acc[qq * 4 + 1] += qv * k4.y;
            acc[qq * 4 + 2] += qv * k4.z;
            acc[qq * 4 + 3] += qv * k4.w;
        }
    }

    const int ng = n0 + n, nh = ng >> 4, nw = ng & 15;
    float lmax = -1e30f;
    #pragma unroll
    for (int i = 0; i < 64; i++) {
        int m = m0 + i, mh = m >> 4, mw = m & 15;
        float bvv = Rs[(nh - mh + 15) * 31 + (nw - mw + 15)];
        float s = acc[i] * 0.125f + bvv;
        acc[i] = s;
        lmax = fmaxf(lmax, s);
    }
    pr[n * 4 + mb] = lmax;
    __syncthreads();
    if (tid < 64)
        rv[tid] = fmaxf(fmaxf(pr[tid * 4 + 0], pr[tid * 4 + 1]),
                        fmaxf(pr[tid * 4 + 2], pr[tid * 4 + 3]));
    __syncthreads();
    const float rm = rv[n];
    float lsum = 0.f;
    #pragma unroll
    for (int i = 0; i < 64; i++) {
        float e = fast_exp(acc[i] - rm);
        acc[i] = e;
        lsum += e;
    }
    pr[n * 4 + mb] = lsum;
    __syncthreads();
    if (tid < 64)
        rv[tid] = 1.f / (pr[tid * 4 + 0] + pr[tid * 4 + 1] +
                         pr[tid * 4 + 2] + pr[tid * 4 + 3]);
    __syncthreads();
    const float inv = rv[n];
    #pragma unroll
    for (int i = 0; i < 64; i++) Ss[n * 257 + m0 + i] = acc[i] * inv;
    __syncthreads();

    const int dg = (tid & 15) * 4;
    const int nb = (tid >> 4) * 4;
    float o2[4][4];
    #pragma unroll
    for (int j = 0; j < 4; j++)
        #pragma unroll
        for (int i = 0; i < 4; i++) o2[j][i] = 0.f;

    #pragma unroll 4
    for (int m = 0; m < 256; m++) {
        float4 v4 = *(const float4*)&Vs[m * 68 + dg];
        #pragma unroll
        for (int j = 0; j < 4; j++) {
            float s = Ss[(nb + j) * 257 + m];
            o2[j][0] += s * v4.x;
            o2[j][1] += s * v4.y;
            o2[j][2] += s * v4.z;
            o2[j][3] += s * v4.w;
        }
    }

    float* og = g_att + ((size_t)b * CH + h * HD) * NPIX + n0;
    #pragma unroll
    for (int j = 0; j < 4; j++)
        #pragma unroll
        for (int i = 0; i < 4; i++)
            og[(size_t)(dg + i) * NPIX + nb + j] = o2[j][i];
}

// ---------------------------------------------------------------------------
extern "C" void kernel_launch(void* const* d_in, const int* in_sizes, int n_in,
                              void* d_out, int out_size)
{
    const float* x      = (const float*)d_in[0];
    const float* qkv_w  = (const float*)d_in[1];
    const float* qkv_b  = (const float*)d_in[2];
    const float* out_w  = (const float*)d_in[3];
    const float* out_b  = (const float*)d_in[4];
    const float* rel    = (const float*)d_in[5];
    float* out = (float*)d_out;

    void* p_qkv = nullptr;
    void* p_att = nullptr;
    cudaGetSymbolAddress(&p_qkv, g_qkv);
    cudaGetSymbolAddress(&p_att, g_att);

    cudaFuncSetAttribute(attn_kernel,
                         cudaFuncAttributeMaxDynamicSharedMemorySize, ATTN_SMEM_BYTES);

    // 1) QKV projection (mma.sync bf16, 2-way split)
    gemm_mma<3 * CH><<<dim3(NPIX / 64, (3 * CH) / 64, BATCH), 128>>>(
        qkv_w, x, qkv_b, (float*)p_qkv);

    // 2) Attention with relative-position bias
    attn_kernel<<<dim3(NPIX / 64, HEADS, BATCH), 256, ATTN_SMEM_BYTES>>>(rel);

    // 3) Output projection
    gemm_mma<CH><<<dim3(NPIX / 64, CH / 64, BATCH), 128>>>(
        out_w, (const float*)p_att, out_b, out);
}

// round 4
// speedup vs baseline: 2.7341x; 1.5657x over previous
#include <cuda_runtime.h>
#include <cstdint>
#include <math.h>

#define BATCH 64
#define CH    512
#define NPIX  256
#define HEADS 8
#define HD    64

// Scratch (no cudaMalloc allowed) -----------------------------------------
__device__ float g_qkv[(size_t)BATCH * 3 * CH * NPIX];  // [b][o][p]
__device__ float g_att[(size_t)BATCH * CH * NPIX];      // [b][c][p]

// ======================= helpers ==========================================
__device__ __forceinline__ uint32_t smem_to_u32(const void* p) {
    uint32_t a;
    asm("{ .reg .u64 t; cvta.to.shared.u64 t, %1; cvt.u32.u64 %0, t; }"
        : "=r"(a) : "l"(p));
    return a;
}

// pack two floats -> bf16x2 (hi half = f_hi, lo half = f_lo)
__device__ __forceinline__ uint32_t pack_bf16x2(float f_hi, float f_lo) {
    uint32_t r;
    asm("cvt.rn.bf16x2.f32 %0, %1, %2;" : "=r"(r) : "f"(f_hi), "f"(f_lo));
    return r;
}
__device__ __forceinline__ float bf_lo(uint32_t h) { return __uint_as_float(h << 16); }
__device__ __forceinline__ float bf_hi(uint32_t h) { return __uint_as_float(h & 0xFFFF0000u); }

__device__ __forceinline__ void ldm_x4(uint32_t* r, uint32_t addr) {
    asm volatile("ldmatrix.sync.aligned.m8n8.x4.shared.b16 {%0,%1,%2,%3}, [%4];"
        : "=r"(r[0]), "=r"(r[1]), "=r"(r[2]), "=r"(r[3]) : "r"(addr));
}
__device__ __forceinline__ void ldm_x4_t(uint32_t* r, uint32_t addr) {
    asm volatile("ldmatrix.sync.aligned.m8n8.x4.trans.shared.b16 {%0,%1,%2,%3}, [%4];"
        : "=r"(r[0]), "=r"(r[1]), "=r"(r[2]), "=r"(r[3]) : "r"(addr));
}

__device__ __forceinline__ void mma_bf16(float* c, const uint32_t* a,
                                         const uint32_t* b) {
    asm volatile(
        "mma.sync.aligned.m16n8k16.row.col.f32.bf16.bf16.f32 "
        "{%0,%1,%2,%3}, {%4,%5,%6,%7}, {%8,%9}, {%0,%1,%2,%3};"
        : "+f"(c[0]), "+f"(c[1]), "+f"(c[2]), "+f"(c[3])
        : "r"(a[0]), "r"(a[1]), "r"(a[2]), "r"(a[3]), "r"(b[0]), "r"(b[1]));
}

// exp via FMA pipe, |relerr|<3e-6
__device__ __forceinline__ float fast_exp(float t) {
    float y = t * 1.4426950408889634f;
    y = fmaxf(y, -126.0f);
    int ni = __float2int_rn(y);
    float f = y - (float)ni;
    float p = 1.3333558146428443e-3f;
    p = fmaf(p, f, 9.618129842071803e-3f);
    p = fmaf(p, f, 5.550410866482158e-2f);
    p = fmaf(p, f, 2.402265069591007e-1f);
    p = fmaf(p, f, 6.931471805599453e-1f);
    p = fmaf(p, f, 1.0f);
    return __uint_as_float(__float_as_uint(p) + ((uint32_t)ni << 23));
}

// hi/lo bf16 split of a float4, stored as 2x uint2
__device__ __forceinline__ void split_sts(char* hdst, char* ldst, float4 v) {
    uint32_t h0 = pack_bf16x2(v.y, v.x);
    uint32_t h1 = pack_bf16x2(v.w, v.z);
    uint32_t l0 = pack_bf16x2(v.y - bf_hi(h0), v.x - bf_lo(h0));
    uint32_t l1 = pack_bf16x2(v.w - bf_hi(h1), v.z - bf_lo(h1));
    *(uint2*)hdst = make_uint2(h0, h1);
    *(uint2*)ldst = make_uint2(l0, l1);
}

// ---------------------------------------------------------------------------
// GEMM via mma.sync bf16 (2-way split, 3 terms)  -- unchanged from R3
// ---------------------------------------------------------------------------
#define A_HI 0
#define A_LO 5120
#define B_HI 10240
#define B_LO 15360
#define GEMM_SMEM_BYTES 20480

template <int M>
__global__ __launch_bounds__(128, 1) void gemm_mma(
    const float* __restrict__ W, const float* __restrict__ X,
    const float* __restrict__ bias, float* __restrict__ Y)
{
    __shared__ __align__(128) char smem[GEMM_SMEM_BYTES];
    const uint32_t sb = smem_to_u32(smem);

    const int tid = threadIdx.x;
    const int wid = tid >> 5;
    const int lid = tid & 31;
    const int wm = wid >> 1;
    const int wn = wid & 1;
    const int p0 = blockIdx.x * 64;
    const int m0 = blockIdx.y * 64;
    const int b  = blockIdx.z;

    const int am  = tid >> 3;
    const int akq = tid & 7;
    const float* wp = W + (size_t)(m0 + am) * CH + akq * 4;
    const int bn = tid & 63;
    const int bg = tid >> 6;
    const float* xp = X + (size_t)b * CH * NPIX + p0 + bn;

    const uint32_t aoff = (uint32_t)(wm * 32 + (lid & 15)) * 80 + (lid >> 4) * 16;
    const uint32_t aAH0 = sb + A_HI + aoff;
    const uint32_t aAL0 = sb + A_LO + aoff;
    const int q = lid >> 3;
    const uint32_t boff =
        (uint32_t)(wn * 32 + ((q >> 1) & 1) * 8 + (lid & 7)) * 80 + (q & 1) * 16;
    const uint32_t aBH0 = sb + B_HI + boff;
    const uint32_t aBL0 = sb + B_LO + boff;

    float acc[2][4][4];
    #pragma unroll
    for (int mi = 0; mi < 2; mi++)
        #pragma unroll
        for (int nj = 0; nj < 4; nj++)
            #pragma unroll
            for (int e = 0; e < 4; e++) acc[mi][nj][e] = 0.f;

    float4 ra[4];
    float  rb[16];
    #pragma unroll
    for (int i = 0; i < 4; i++)
        ra[i] = *(const float4*)(wp + (size_t)(16 * i) * CH);
    #pragma unroll
    for (int j = 0; j < 16; j++)
        rb[j] = xp[(size_t)(bg * 16 + j) * NPIX];

    #pragma unroll 1
    for (int c = 0; c < 16; c++) {
        #pragma unroll
        for (int i = 0; i < 4; i++) {
            uint32_t off = (uint32_t)(am + 16 * i) * 80 + akq * 8;
            split_sts(smem + A_HI + off, smem + A_LO + off, ra[i]);
        }
        {
            uint32_t base = (uint32_t)bn * 80 + bg * 32;
            #pragma unroll
            for (int qq = 0; qq < 4; qq++) {
                float4 v = make_float4(rb[qq * 4 + 0], rb[qq * 4 + 1],
                                       rb[qq * 4 + 2], rb[qq * 4 + 3]);
                split_sts(smem + B_HI + base + qq * 8,
                          smem + B_LO + base + qq * 8, v);
            }
        }
        __syncthreads();

        if (c < 15) {
            const int k0 = (c + 1) * 32;
            #pragma unroll
            for (int i = 0; i < 4; i++)
                ra[i] = *(const float4*)(wp + (size_t)(16 * i) * CH + k0);
            #pragma unroll
            for (int j = 0; j < 16; j++)
                rb[j] = xp[(size_t)(k0 + bg * 16 + j) * NPIX];
        }

        #pragma unroll
        for (int ks = 0; ks < 2; ks++) {
            const uint32_t kb = ks * 32;
            uint32_t ah[2][4], al[2][4], bh[2][4], bl[2][4];
            ldm_x4(ah[0], aAH0 + kb);
            ldm_x4(ah[1], aAH0 + 16 * 80 + kb);
            ldm_x4(al[0], aAL0 + kb);
            ldm_x4(al[1], aAL0 + 16 * 80 + kb);
            ldm_x4(bh[0], aBH0 + kb);
            ldm_x4(bh[1], aBH0 + 16 * 80 + kb);
            ldm_x4(bl[0], aBL0 + kb);
            ldm_x4(bl[1], aBL0 + 16 * 80 + kb);

            #pragma unroll
            for (int mi = 0; mi < 2; mi++)
                #pragma unroll
                for (int nj = 0; nj < 4; nj++) {
                    const uint32_t* bhp = &bh[nj >> 1][(nj & 1) * 2];
                    const uint32_t* blp = &bl[nj >> 1][(nj & 1) * 2];
                    mma_bf16(acc[mi][nj], ah[mi], bhp);
                    mma_bf16(acc[mi][nj], ah[mi], blp);
                    mma_bf16(acc[mi][nj], al[mi], bhp);
                }
        }
        __syncthreads();
    }

    #pragma unroll
    for (int mi = 0; mi < 2; mi++) {
        const int rr = wm * 32 + mi * 16 + (lid >> 2);
        const float bv0 = __ldg(&bias[m0 + rr]);
        const float bv1 = __ldg(&bias[m0 + rr + 8]);
        float* y0 = Y + ((size_t)b * M + m0 + rr) * NPIX + p0 + wn * 32 + (lid & 3) * 2;
        float* y1 = y0 + 8 * NPIX;
        #pragma unroll
        for (int nj = 0; nj < 4; nj++) {
            float2 v0 = make_float2(acc[mi][nj][0] + bv0, acc[mi][nj][1] + bv0);
            float2 v1 = make_float2(acc[mi][nj][2] + bv1, acc[mi][nj][3] + bv1);
            *(float2*)(y0 + nj * 8) = v0;
            *(float2*)(y1 + nj * 8) = v1;
        }
    }
}

// ---------------------------------------------------------------------------
// Attention on tensor cores. CTA = (64-query tile, head, batch), 256 threads.
// 8 warps: wn = wid&3 (16 query rows), wm = wid>>2 (half of the 256 keys).
// S (64x256) lives in mma accumulators; softmax in registers (+tiny smem
// cross-warp reduce); P repacked to A fragments in registers; O (64x64)
// accumulated in registers, cross-wm reduced through K's dead smem.
// Layouts (bf16 hi/lo): Qs[d=64][n=64] stride 144B; Ks[d=64][m=256] stride
// 528B; Vs[d=64][m=256] stride 528B. All odd multiples of 16B (no LDSM
// conflicts); S operands via ldmatrix.trans, V via non-trans.
// ---------------------------------------------------------------------------
#define AT_QH   0
#define AT_QL   9216
#define AT_KH   18432
#define AT_KL   52224
#define AT_VH   86016
#define AT_VL   119808
#define AT_REL  153600      // 961 floats (padded to 3856B)
#define AT_MAXB 157456      // [2][64] float
#define AT_SUMB 157968      // [2][64] float
#define AT_RS   158480      // [64] float
#define AT_SMEM 158736
// O partials overlay (after S phase K is dead): [2][64][68] fp32 at AT_KH

__global__ __launch_bounds__(256, 1) void attn_mma(const float* __restrict__ rel)
{
    extern __shared__ char sm[];
    float* smf = (float*)sm;
    const uint32_t sb = smem_to_u32(sm);

    const int tid  = threadIdx.x;
    const int lane = tid & 31;
    const int wid  = tid >> 5;
    const int wn   = wid & 3;
    const int wm   = wid >> 2;
    const int n0g  = blockIdx.x * 64;
    const int h    = blockIdx.y;
    const int b    = blockIdx.z;

    const float* qkv = g_qkv + (size_t)b * (3 * CH * NPIX);
    const float* qg = qkv + (h * HD) * NPIX;
    const float* kg = qkv + (CH + h * HD) * NPIX;
    const float* vg = qkv + (2 * CH + h * HD) * NPIX;

    // ---- convert Q,K,V to bf16 hi/lo in smem (natural [d][token] layout) --
    #pragma unroll
    for (int it = 0; it < 4; it++) {               // Q: 64d x 64n
        int i = tid + it * 256;
        int d = i >> 4, nq = (i & 15) * 4;
        float4 v = *(const float4*)&qg[d * NPIX + n0g + nq];
        split_sts(sm + AT_QH + d * 144 + nq * 2, sm + AT_QL + d * 144 + nq * 2, v);
    }
    #pragma unroll
    for (int it = 0; it < 16; it++) {              // K: 64d x 256m
        int i = tid + it * 256;
        int d = i >> 6, mq = (i & 63) * 4;
        float4 v = *(const float4*)&kg[d * NPIX + mq];
        split_sts(sm + AT_KH + d * 528 + mq * 2, sm + AT_KL + d * 528 + mq * 2, v);
    }
    #pragma unroll
    for (int it = 0; it < 16; it++) {              // V: 64d x 256m
        int i = tid + it * 256;
        int d = i >> 6, mq = (i & 63) * 4;
        float4 v = *(const float4*)&vg[d * NPIX + mq];
        split_sts(sm + AT_VH + d * 528 + mq * 2, sm + AT_VL + d * 528 + mq * 2, v);
    }
    for (int i = tid; i < 961; i += 256)
        smf[AT_REL / 4 + i] = rel[h * 961 + i];
    __syncthreads();

    // ---- S = Q^T K (+3-term split) ---------------------------------------
    float acc[16][4];
    #pragma unroll
    for (int f = 0; f < 16; f++)
        #pragma unroll
        for (int e = 0; e < 4; e++) acc[f][e] = 0.f;

    // ldmatrix.trans lane address components
    const uint32_t a_row = ((lane >> 4) & 1) * 8 + (lane & 7);   // A: k(d) rows
    const uint32_t a_col = (uint32_t)(wn * 16 + ((lane >> 3) & 1) * 8) * 2;
    const uint32_t b_row = ((lane >> 3) & 1) * 8 + (lane & 7);   // B: k(d) rows
    const uint32_t b_col8 = ((lane >> 4) & 1) * 8;

    #pragma unroll
    for (int s = 0; s < 4; s++) {
        uint32_t ah[4], al[4];
        ldm_x4_t(ah, sb + AT_QH + (s * 16 + a_row) * 144 + a_col);
        ldm_x4_t(al, sb + AT_QL + (s * 16 + a_row) * 144 + a_col);
        #pragma unroll
        for (int mg = 0; mg < 8; mg++) {
            const uint32_t mcol = (uint32_t)(wm * 128 + mg * 16 + b_col8) * 2;
            uint32_t bh[4], bl[4];
            ldm_x4_t(bh, sb + AT_KH + (s * 16 + b_row) * 528 + mcol);
            ldm_x4_t(bl, sb + AT_KL + (s * 16 + b_row) * 528 + mcol);
            mma_bf16(acc[2 * mg], ah, &bh[0]);
            mma_bf16(acc[2 * mg], ah, &bl[0]);
            mma_bf16(acc[2 * mg], al, &bh[0]);
            mma_bf16(acc[2 * mg + 1], ah, &bh[2]);
            mma_bf16(acc[2 * mg + 1], ah, &bl[2]);
            mma_bf16(acc[2 * mg + 1], al, &bh[2]);
        }
    }

    // ---- scale + rel-pos bias, row max ------------------------------------
    const int rq  = lane >> 2;
    const int nr  = n0g + wn * 16 + rq;
    const int nr8 = nr + 8;
    const int nb0 = (nr >> 4) * 31 + (nr & 15) + 480;
    const int nb8 = (nr8 >> 4) * 31 + (nr8 & 15) + 480;
    const float* Rs = smf + AT_REL / 4;

    float mx0 = -1e30f, mx8 = -1e30f;
    #pragma unroll
    for (int f = 0; f < 16; f++) {
        int mc = wm * 128 + f * 8 + (lane & 3) * 2;
        int mi0 = (mc >> 4) * 31 + (mc & 15);
        int mi1 = ((mc + 1) >> 4) * 31 + ((mc + 1) & 15);
        acc[f][0] = fmaf(acc[f][0], 0.125f, Rs[nb0 - mi0]);
        acc[f][1] = fmaf(acc[f][1], 0.125f, Rs[nb0 - mi1]);
        acc[f][2] = fmaf(acc[f][2], 0.125f, Rs[nb8 - mi0]);
        acc[f][3] = fmaf(acc[f][3], 0.125f, Rs[nb8 - mi1]);
        mx0 = fmaxf(mx0, fmaxf(acc[f][0], acc[f][1]));
        mx8 = fmaxf(mx8, fmaxf(acc[f][2], acc[f][3]));
    }
    mx0 = fmaxf(mx0, __shfl_xor_sync(0xFFFFFFFF, mx0, 1));
    mx0 = fmaxf(mx0, __shfl_xor_sync(0xFFFFFFFF, mx0, 2));
    mx8 = fmaxf(mx8, __shfl_xor_sync(0xFFFFFFFF, mx8, 1));
    mx8 = fmaxf(mx8, __shfl_xor_sync(0xFFFFFFFF, mx8, 2));
    float* maxb = smf + AT_MAXB / 4;
    const int row = wn * 16 + rq;
    if ((lane & 3) == 0) {
        maxb[wm * 64 + row]     = mx0;
        maxb[wm * 64 + row + 8] = mx8;
    }
    __syncthreads();
    mx0 = fmaxf(maxb[row],     maxb[64 + row]);
    mx8 = fmaxf(maxb[row + 8], maxb[64 + row + 8]);

    // ---- exp + row sum -----------------------------------------------------
    float s0 = 0.f, s8 = 0.f;
    #pragma unroll
    for (int f = 0; f < 16; f++) {
        acc[f][0] = fast_exp(acc[f][0] - mx0);
        acc[f][1] = fast_exp(acc[f][1] - mx0);
        acc[f][2] = fast_exp(acc[f][2] - mx8);
        acc[f][3] = fast_exp(acc[f][3] - mx8);
        s0 += acc[f][0] + acc[f][1];
        s8 += acc[f][2] + acc[f][3];
    }
    s0 += __shfl_xor_sync(0xFFFFFFFF, s0, 1);
    s0 += __shfl_xor_sync(0xFFFFFFFF, s0, 2);
    s8 += __shfl_xor_sync(0xFFFFFFFF, s8, 1);
    s8 += __shfl_xor_sync(0xFFFFFFFF, s8, 2);
    float* sumb = smf + AT_SUMB / 4;
    if ((lane & 3) == 0) {
        sumb[wm * 64 + row]     = s0;
        sumb[wm * 64 + row + 8] = s8;
    }
    __syncthreads();
    if (wm == 0 && (lane & 3) == 0) {
        smf[AT_RS / 4 + row]     = 1.f / (sumb[row] + sumb[64 + row]);
        smf[AT_RS / 4 + row + 8] = 1.f / (sumb[row + 8] + sumb[64 + row + 8]);
    }

    // ---- repack P (unnormalized) into A-fragments (hi/lo) ------------------
    uint32_t ph[16][2], pl[16][2];
    #pragma unroll
    for (int f = 0; f < 16; f++) {
        uint32_t h01 = pack_bf16x2(acc[f][1], acc[f][0]);
        uint32_t h23 = pack_bf16x2(acc[f][3], acc[f][2]);
        pl[f][0] = pack_bf16x2(acc[f][1] - bf_hi(h01), acc[f][0] - bf_lo(h01));
        pl[f][1] = pack_bf16x2(acc[f][3] - bf_hi(h23), acc[f][2] - bf_lo(h23));
        ph[f][0] = h01;
        ph[f][1] = h23;
    }

    // ---- O_partial = P V^T  (k = this warp's 128 keys) ---------------------
    float oacc[8][4];
    #pragma unroll
    for (int g = 0; g < 8; g++)
        #pragma unroll
        for (int e = 0; e < 4; e++) oacc[g][e] = 0.f;

    const uint32_t v_row = ((lane >> 4) & 1) * 8 + (lane & 7);   // non-trans
    const uint32_t v_colh = ((lane >> 3) & 1) * 16;

    #pragma unroll
    for (int s = 0; s < 8; s++) {
        uint32_t a_h[4] = {ph[2 * s][0], ph[2 * s][1], ph[2 * s + 1][0], ph[2 * s + 1][1]};
        uint32_t a_l[4] = {pl[2 * s][0], pl[2 * s][1], pl[2 * s + 1][0], pl[2 * s + 1][1]};
        const uint32_t vcol = (uint32_t)(wm * 128 + s * 16) * 2 + v_colh;
        #pragma unroll
        for (int dg = 0; dg < 4; dg++) {
            uint32_t bh[4], bl[4];
            const uint32_t vaddr = (dg * 16 + v_row) * 528 + vcol;
            ldm_x4(bh, sb + AT_VH + vaddr);
            ldm_x4(bl, sb + AT_VL + vaddr);
            mma_bf16(oacc[2 * dg], a_h, &bh[0]);
            mma_bf16(oacc[2 * dg], a_h, &bl[0]);
            mma_bf16(oacc[2 * dg], a_l, &bh[0]);
            mma_bf16(oacc[2 * dg + 1], a_h, &bh[2]);
            mma_bf16(oacc[2 * dg + 1], a_h, &bl[2]);
            mma_bf16(oacc[2 * dg + 1], a_l, &bh[2]);
        }
    }

    // ---- cross-wm O reduce via smem (overlays dead K region) ---------------
    float* Osm = smf + AT_KH / 4;              // [2][64][68]
    #pragma unroll
    for (int g = 0; g < 8; g++) {
        int d = g * 8 + (lane & 3) * 2;
        float* p0 = Osm + (wm * 64 + d) * 68 + row;
        float* p1 = Osm + (wm * 64 + d + 1) * 68 + row;
        p0[0] = oacc[g][0];
        p1[0] = oacc[g][1];
        p0[8] = oacc[g][2];
        p1[8] = oacc[g][3];
    }
    __syncthreads();

    // ---- final: sum halves, normalize, coalesced store ---------------------
    {
        const int d  = tid >> 2;
        const int nq = (tid & 3) * 16;
        const float* rs = smf + AT_RS / 4;
        float* og = g_att + ((size_t)b * CH + h * HD + d) * NPIX + n0g;
        #pragma unroll
        for (int j = 0; j < 4; j++) {
            int n = nq + j * 4;
            float4 x0 = *(float4*)&Osm[d * 68 + n];
            float4 x1 = *(float4*)&Osm[(64 + d) * 68 + n];
            float4 r  = *(float4*)&rs[n];
            float4 o;
            o.x = (x0.x + x1.x) * r.x;
            o.y = (x0.y + x1.y) * r.y;
            o.z = (x0.z + x1.z) * r.z;
            o.w = (x0.w + x1.w) * r.w;
            *(float4*)&og[n] = o;
        }
    }
}

// ---------------------------------------------------------------------------
extern "C" void kernel_launch(void* const* d_in, const int* in_sizes, int n_in,
                              void* d_out, int out_size)
{
    const float* x      = (const float*)d_in[0];
    const float* qkv_w  = (const float*)d_in[1];
    const float* qkv_b  = (const float*)d_in[2];
    const float* out_w  = (const float*)d_in[3];
    const float* out_b  = (const float*)d_in[4];
    const float* rel    = (const float*)d_in[5];
    float* out = (float*)d_out;

    void* p_qkv = nullptr;
    void* p_att = nullptr;
    cudaGetSymbolAddress(&p_qkv, g_qkv);
    cudaGetSymbolAddress(&p_att, g_att);

    cudaFuncSetAttribute(attn_mma,
                         cudaFuncAttributeMaxDynamicSharedMemorySize, AT_SMEM);

    // 1) QKV projection
    gemm_mma<3 * CH><<<dim3(NPIX / 64, (3 * CH) / 64, BATCH), 128>>>(
        qkv_w, x, qkv_b, (float*)p_qkv);

    // 2) Attention (tensor cores)
    attn_mma<<<dim3(NPIX / 64, HEADS, BATCH), 256, AT_SMEM>>>(rel);

    // 3) Output projection
    gemm_mma<CH><<<dim3(NPIX / 64, CH / 64, BATCH), 128>>>(
        out_w, (const float*)p_att, out_b, out);
}